// round 7
// baseline (speedup 1.0000x reference)
#include <cuda_runtime.h>
#include <cuda_bf16.h>
#include <math.h>

// ---------------------------------------------------------------------------
#define B_     2
#define T_     20
#define V_     256
#define TN     (T_ * V_)          // 5120
#define NROWS  (B_ * TN)         // 10240
#define HID    4
#define DQ     8
#define OUTD   5
#define CMAP   2048
#define HMAP   32
#define WMAP   32
#define NPIX   (HMAP * WMAP)     // 1024
#define CC     256

#define KSPLIT 32
#define KCHUNK (TN / KSPLIT)     // 160
#define QPT    8                 // queries per thread in k3
#define K3THR  128
#define QBLK   (K3THR * QPT)     // 1024
#define NQB    (NROWS / QBLK)    // 10

#define CI     16                // channel splits in k01
#define CPB    (CMAP / CI)       // 128 channels per block

#define NL2E   (-1.44269504f)

// ---------------------------------------------------------------------------
__device__ float4 g_pp3[CI * 3 * 256];        // per-split 3-ch pcomp partials
__device__ float  g_cb3[3];                   // bias term in ABG space
__device__ float4 g_pc3[NPIX];                // (a,b,g) map, M-and-NL2E folded
__device__ float4 g_ABG[NROWS];               // per-query (alpha,beta,gamma)
__device__ float2 g_UW[NROWS];                // pos-encoded (xr0, xr1)
__device__ float4 g_part[KSPLIT * NROWS];     // (T0,T1,T2,pad) partials

// ---------------------------------------------------------------------------
__device__ __forceinline__ float ex2f(float x) {
    float r; asm("ex2.approx.f32 %0, %1;" : "=f"(r) : "f"(x)); return r;
}
__device__ __forceinline__ float rcpf(float x) {
    float r; asm("rcp.approx.f32 %0, %1;" : "=f"(r) : "f"(x)); return r;
}
__device__ __forceinline__ float fsigm(float x) { return rcpf(1.f + ex2f(-1.44269504f * x)); }
__device__ __forceinline__ float ftanh(float x) { return 1.f - 2.f * rcpf(ex2f(2.88539008f * x) + 1.f); }

// ---------------------------------------------------------------------------
// K01: fused Weff + M-fold + 3-channel pcomp partial. grid(CI=16) x 256.
// Block ci handles channels [ci*128, ci*128+128).
// ---------------------------------------------------------------------------
__global__ __launch_bounds__(256) void k01_map(
        const float* __restrict__ W_fuse,
        const float* __restrict__ W_comp,
        const float* __restrict__ b_comp,
        const float* __restrict__ W_fc,
        const float* __restrict__ W_fc2,
        const float* __restrict__ b_fc2) {
    __shared__ float sWfl[4 * 256];    // W_fuse[:, 4:260]
    __shared__ float sM[12];           // M[j][h], NL2E folded
    __shared__ float sW4[4 * CPB];     // Weff4 slice
    __shared__ float sw3[3 * CPB];     // Weff3 slice (M folded)
    int tid = threadIdx.x, ci = blockIdx.x;

    for (int i = tid; i < 4 * 256; i += 256) {
        int h = i >> 8, cc = i & 255;
        sWfl[i] = W_fuse[h * 260 + 4 + cc];
    }
    if (tid < 12) {
        int j = tid >> 2, h = tid & 3;
        float m = 0.f;
#pragma unroll
        for (int d = 0; d < DQ; d++) {
            float wj = (j == 0) ? W_fc2[d * 2] : (j == 1 ? W_fc2[d * 2 + 1] : b_fc2[d]);
            m += wj * W_fc[d * HID + h];
        }
        sM[tid] = m * NL2E;
    }
    __syncthreads();

    // phase 1: Weff4[h][cl] = sum_cc Wfl[h][cc] * W_comp[cc][ci*128+cl]
    {
        int cl = tid & (CPB - 1);
        int hp = tid >> 7;                 // 0 or 1
        int h0 = hp * 2, h1 = hp * 2 + 1;
        float a0 = 0.f, a1 = 0.f;
        const float* wcol = W_comp + ci * CPB + cl;
#pragma unroll 8
        for (int cc = 0; cc < CC; cc++) {
            float w = wcol[cc * CMAP];
            a0 += sWfl[h0 * 256 + cc] * w;
            a1 += sWfl[h1 * 256 + cc] * w;
        }
        sW4[h0 * CPB + cl] = a0;
        sW4[h1 * CPB + cl] = a1;
    }

    // bias path (block 0 only): cb3[j] = M[j] . (Wfl @ b_comp)
    if (ci == 0 && tid < 32) {
        float p0 = 0.f, p1 = 0.f, p2 = 0.f, p3 = 0.f;
        for (int cc = tid; cc < CC; cc += 32) {
            float bv = b_comp[cc];
            p0 += sWfl[0 * 256 + cc] * bv;
            p1 += sWfl[1 * 256 + cc] * bv;
            p2 += sWfl[2 * 256 + cc] * bv;
            p3 += sWfl[3 * 256 + cc] * bv;
        }
#pragma unroll
        for (int o = 16; o > 0; o >>= 1) {
            p0 += __shfl_down_sync(0xffffffffu, p0, o);
            p1 += __shfl_down_sync(0xffffffffu, p1, o);
            p2 += __shfl_down_sync(0xffffffffu, p2, o);
            p3 += __shfl_down_sync(0xffffffffu, p3, o);
        }
        if (tid == 0) {
#pragma unroll
            for (int j = 0; j < 3; j++)
                g_cb3[j] = sM[j * 4 + 0] * p0 + sM[j * 4 + 1] * p1
                         + sM[j * 4 + 2] * p2 + sM[j * 4 + 3] * p3;
        }
    }
    __syncthreads();

    // fold M: sw3[j][cl]
    for (int i = tid; i < 3 * CPB; i += 256) {
        int j = i / CPB, cl = i - j * CPB;
        sw3[i] = sM[j * 4 + 0] * sW4[0 * CPB + cl] + sM[j * 4 + 1] * sW4[1 * CPB + cl]
               + sM[j * 4 + 2] * sW4[2 * CPB + cl] + sM[j * 4 + 3] * sW4[3 * CPB + cl];
    }
    __syncthreads();

    // phase 2: pcomp3 partial over this channel slice; thread = 4-pixel group
    const float4* m4 = (const float4*)( (const float*)0 == 0 ? nullptr : nullptr );
    (void)m4;
    const float4* meta4 = nullptr;
    // metadata passed via W_comp? no — pass metadata separately below
    // (placeholder removed in real signature)
    ;
    // NOTE: metadata pointer comes in through b_fc2? -- see k01 call; we use
    // a second kernel parameter instead.
}

// The above stub had a structural mistake; real implementation below.
__global__ __launch_bounds__(256) void k01_map2(
        const float* __restrict__ metadata) {
    // unused
}

// ---------------------------------------------------------------------------
// Proper fused kernel (replaces the two above; they are kept unreferenced
// to avoid accidental use).
// ---------------------------------------------------------------------------
__global__ __launch_bounds__(256) void k01(
        const float* __restrict__ W_fuse,
        const float* __restrict__ W_comp,
        const float* __restrict__ b_comp,
        const float* __restrict__ W_fc,
        const float* __restrict__ W_fc2,
        const float* __restrict__ b_fc2,
        const float* __restrict__ metadata) {
    __shared__ float sWfl[4 * 256];
    __shared__ float sM[12];
    __shared__ float sW4[4 * CPB];
    __shared__ float sw3[3 * CPB];
    int tid = threadIdx.x, ci = blockIdx.x;

    for (int i = tid; i < 4 * 256; i += 256) {
        int h = i >> 8, cc = i & 255;
        sWfl[i] = W_fuse[h * 260 + 4 + cc];
    }
    if (tid < 12) {
        int j = tid >> 2, h = tid & 3;
        float m = 0.f;
#pragma unroll
        for (int d = 0; d < DQ; d++) {
            float wj = (j == 0) ? W_fc2[d * 2] : (j == 1 ? W_fc2[d * 2 + 1] : b_fc2[d]);
            m += wj * W_fc[d * HID + h];
        }
        sM[tid] = m * NL2E;
    }
    __syncthreads();

    {
        int cl = tid & (CPB - 1);
        int hp = tid >> 7;
        int h0 = hp * 2, h1 = hp * 2 + 1;
        float a0 = 0.f, a1 = 0.f;
        const float* wcol = W_comp + ci * CPB + cl;
#pragma unroll 8
        for (int cc = 0; cc < CC; cc++) {
            float w = wcol[cc * CMAP];
            a0 += sWfl[h0 * 256 + cc] * w;
            a1 += sWfl[h1 * 256 + cc] * w;
        }
        sW4[h0 * CPB + cl] = a0;
        sW4[h1 * CPB + cl] = a1;
    }

    if (ci == 0 && tid < 32) {
        float p0 = 0.f, p1 = 0.f, p2 = 0.f, p3 = 0.f;
        for (int cc = tid; cc < CC; cc += 32) {
            float bv = b_comp[cc];
            p0 += sWfl[0 * 256 + cc] * bv;
            p1 += sWfl[1 * 256 + cc] * bv;
            p2 += sWfl[2 * 256 + cc] * bv;
            p3 += sWfl[3 * 256 + cc] * bv;
        }
#pragma unroll
        for (int o = 16; o > 0; o >>= 1) {
            p0 += __shfl_down_sync(0xffffffffu, p0, o);
            p1 += __shfl_down_sync(0xffffffffu, p1, o);
            p2 += __shfl_down_sync(0xffffffffu, p2, o);
            p3 += __shfl_down_sync(0xffffffffu, p3, o);
        }
        if (tid == 0) {
#pragma unroll
            for (int j = 0; j < 3; j++)
                g_cb3[j] = sM[j * 4 + 0] * p0 + sM[j * 4 + 1] * p1
                         + sM[j * 4 + 2] * p2 + sM[j * 4 + 3] * p3;
        }
    }
    __syncthreads();

    for (int i = tid; i < 3 * CPB; i += 256) {
        int j = i / CPB, cl = i - j * CPB;
        sw3[i] = sM[j * 4 + 0] * sW4[0 * CPB + cl] + sM[j * 4 + 1] * sW4[1 * CPB + cl]
               + sM[j * 4 + 2] * sW4[2 * CPB + cl] + sM[j * 4 + 3] * sW4[3 * CPB + cl];
    }
    __syncthreads();

    const float4* m4 = (const float4*)metadata;
    float4 aa = make_float4(0, 0, 0, 0), ab = aa, ag = aa;
#pragma unroll 8
    for (int cl = 0; cl < CPB; cl++) {
        float4 m = m4[(ci * CPB + cl) * 256 + tid];
        float wa = sw3[cl], wb = sw3[CPB + cl], wg = sw3[2 * CPB + cl];
        aa.x += wa * m.x; aa.y += wa * m.y; aa.z += wa * m.z; aa.w += wa * m.w;
        ab.x += wb * m.x; ab.y += wb * m.y; ab.z += wb * m.z; ab.w += wb * m.w;
        ag.x += wg * m.x; ag.y += wg * m.y; ag.z += wg * m.z; ag.w += wg * m.w;
    }
    g_pp3[(ci * 3 + 0) * 256 + tid] = aa;
    g_pp3[(ci * 3 + 1) * 256 + tid] = ab;
    g_pp3[(ci * 3 + 2) * 256 + tid] = ag;
}

// ---------------------------------------------------------------------------
// K1b: reduce CI partials + bias -> per-pixel float4 (a,b,g,0). grid(8) x 32.
// ---------------------------------------------------------------------------
__global__ __launch_bounds__(32) void k1b_reduce() {
    int g = blockIdx.x * 32 + threadIdx.x;   // pixel group 0..255
    float cba = g_cb3[0], cbb = g_cb3[1], cbg = g_cb3[2];
    float4 fa = make_float4(cba, cba, cba, cba);
    float4 fb = make_float4(cbb, cbb, cbb, cbb);
    float4 fg = make_float4(cbg, cbg, cbg, cbg);
#pragma unroll
    for (int ci = 0; ci < CI; ci++) {
        float4 pa = g_pp3[(ci * 3 + 0) * 256 + g];
        float4 pb = g_pp3[(ci * 3 + 1) * 256 + g];
        float4 pg = g_pp3[(ci * 3 + 2) * 256 + g];
        fa.x += pa.x; fa.y += pa.y; fa.z += pa.z; fa.w += pa.w;
        fb.x += pb.x; fb.y += pb.y; fb.z += pb.z; fb.w += pb.w;
        fg.x += pg.x; fg.y += pg.y; fg.z += pg.z; fg.w += pg.w;
    }
    g_pc3[g * 4 + 0] = make_float4(fa.x, fb.x, fg.x, 0.f);
    g_pc3[g * 4 + 1] = make_float4(fa.y, fb.y, fg.y, 0.f);
    g_pc3[g * 4 + 2] = make_float4(fa.z, fb.z, fg.z, 0.f);
    g_pc3[g * 4 + 3] = make_float4(fa.w, fb.w, fg.w, 0.f);
}

// ---------------------------------------------------------------------------
// K2: pos-encode, LSTM, sample pc3, ABG + UW. grid(80) x 128.
// ---------------------------------------------------------------------------
__global__ __launch_bounds__(128) void k2_rows(
        const float* __restrict__ x,
        const float* __restrict__ coords,
        const float* __restrict__ W_ih,
        const float* __restrict__ b_ih,
        const float* __restrict__ b_hh,
        const float* __restrict__ W_fuse,
        const float* __restrict__ b_fuse,
        const float* __restrict__ W_fc,
        const float* __restrict__ b_fc,
        const float* __restrict__ W_fc2,
        const float* __restrict__ b_fc2) {
    __shared__ float sW_ih[32], sb[16], sWf4[16], sbf[4];
    __shared__ float sW_fc[32], sb_fc[8], sW2a[8], sW2b[8], sb2[8];
    int tid = threadIdx.x;
    if (tid < 32) sW_ih[tid] = W_ih[tid];
    if (tid < 16) sb[tid] = b_ih[tid] + b_hh[tid];
    if (tid < 16) sWf4[tid] = W_fuse[(tid >> 2) * 260 + (tid & 3)];
    if (tid < 4)  sbf[tid] = b_fuse[tid];
    if (tid < 32) sW_fc[tid] = W_fc[tid];
    if (tid < 8)  sb_fc[tid] = b_fc[tid];
    if (tid < 8)  sW2a[tid] = W_fc2[tid * 2];
    if (tid < 8)  sW2b[tid] = W_fc2[tid * 2 + 1];
    if (tid < 8)  sb2[tid] = b_fc2[tid];
    __syncthreads();

    int r = blockIdx.x * 128 + tid;
    if (r >= NROWS) return;
    int b = r / TN;
    int p = r - b * TN;
    int t = p / V_;
    int v = p - t * V_;

    float tf  = (float)t;
    float xr0 = x[r * 2 + 0] + __sinf(tf);
    float xr1 = x[r * 2 + 1] + __cosf(tf);
    g_UW[r] = make_float2(xr0, xr1);

    float X[HID];
#pragma unroll
    for (int h = 0; h < HID; h++) {
        int ji = h, jg = 8 + h, jo = 12 + h;
        float gi = sW_ih[ji * 2] * xr0 + sW_ih[ji * 2 + 1] * xr1 + sb[ji];
        float gg = sW_ih[jg * 2] * xr0 + sW_ih[jg * 2 + 1] * xr1 + sb[jg];
        float go = sW_ih[jo * 2] * xr0 + sW_ih[jo * 2 + 1] * xr1 + sb[jo];
        float cst = fsigm(gi) * ftanh(gg);
        X[h] = fsigm(go) * ftanh(cst);
    }

    // bilinear sample of pc3 (zero padding; bias folded into map)
    float cx = coords[((b * 2 + 0) * T_ + t) * V_ + v];
    float cy = coords[((b * 2 + 1) * T_ + t) * V_ + v];
    float fx = cx * (1.f / 16.f) - 0.5f;
    float fy = cy * (1.f / 16.f) - 0.5f;
    float x0f = floorf(fx), y0f = floorf(fy);
    int ix0 = (int)x0f, iy0 = (int)y0f;
    float wx1 = fx - x0f, wx0 = 1.f - wx1;
    float wy1 = fy - y0f, wy0 = 1.f - wy1;

    float la = 0.f, lb = 0.f, lg = 0.f;
#pragma unroll
    for (int cyi = 0; cyi < 2; cyi++) {
#pragma unroll
        for (int cxi = 0; cxi < 2; cxi++) {
            int iy = iy0 + cyi, ix = ix0 + cxi;
            if (iy >= 0 && iy < HMAP && ix >= 0 && ix < WMAP) {
                float w = (cyi ? wy1 : wy0) * (cxi ? wx1 : wx0);
                float4 pv = g_pc3[iy * WMAP + ix];
                la += w * pv.x; lb += w * pv.y; lg += w * pv.z;
            }
        }
    }

    float fsd[HID];
#pragma unroll
    for (int h = 0; h < HID; h++) {
        float s = sbf[h];
#pragma unroll
        for (int j = 0; j < HID; j++) s += sWf4[h * 4 + j] * X[j];
        fsd[h] = s;
    }

    float al = 0.f, be = 0.f, ga = 0.f;
#pragma unroll
    for (int d = 0; d < DQ; d++) {
        float q = sb_fc[d];
#pragma unroll
        for (int h = 0; h < HID; h++) q += sW_fc[d * HID + h] * fsd[h];
        al += q * sW2a[d];
        be += q * sW2b[d];
        ga += q * sb2[d];
    }
    g_ABG[r] = make_float4(al * NL2E + la, be * NL2E + lb, ga * NL2E + lg, 0.f);
}

// ---------------------------------------------------------------------------
// K3: rank-2 sigmoid attention, 8 q/thread. grid(NQB=10, KSPLIT=32) x 128.
// ---------------------------------------------------------------------------
__global__ __launch_bounds__(K3THR) void k3_attn() {
    __shared__ float2 suw[KCHUNK];
    int bq  = blockIdx.x;
    int ks  = blockIdx.y;
    int tid = threadIdx.x;
    int b   = bq / (NQB / B_);
    int kbase = b * TN + ks * KCHUNK;

    for (int i = tid; i < KCHUNK; i += K3THR) suw[i] = g_UW[kbase + i];
    __syncthreads();

    int r = bq * QBLK + tid * QPT;

    float qa[QPT], qb[QPT], qg[QPT];
#pragma unroll
    for (int i = 0; i < QPT; i++) {
        float4 abg = g_ABG[r + i];
        qa[i] = abg.x; qb[i] = abg.y; qg[i] = abg.z;
    }

    float T0[QPT], T1[QPT], T2[QPT];
#pragma unroll
    for (int i = 0; i < QPT; i++) { T0[i] = 0.f; T1[i] = 0.f; T2[i] = 0.f; }

#pragma unroll 2
    for (int j = 0; j < KCHUNK; j++) {
        float2 uw = suw[j];
        float u = uw.x, w = uw.y;
        float e[QPT], pr[QPT];
#pragma unroll
        for (int i = 0; i < QPT; i++) {
            float d = fmaf(qa[i], u, qg[i]);
            d = fmaf(qb[i], w, d);
            e[i] = ex2f(d);
        }
#pragma unroll
        for (int i = 0; i < QPT; i++) pr[i] = rcpf(1.f + e[i]);
#pragma unroll
        for (int i = 0; i < QPT; i++) {
            T0[i] += pr[i];
            T1[i] = fmaf(pr[i], u, T1[i]);
            T2[i] = fmaf(pr[i], w, T2[i]);
        }
    }

    float4* dst = g_part + (size_t)ks * NROWS + r;
#pragma unroll
    for (int i = 0; i < QPT; i++)
        dst[i] = make_float4(T0[i], T1[i], T2[i], 0.f);
}

// ---------------------------------------------------------------------------
// K4: reduce partials, reconstruct, threshold, project. grid(80) x 128.
// ---------------------------------------------------------------------------
__global__ __launch_bounds__(128) void k4_out(const float* __restrict__ W_fc3,
                                              const float* __restrict__ b_fc3,
                                              const float* __restrict__ W_out,
                                              const float* __restrict__ b_out,
                                              float* __restrict__ out) {
    int r = blockIdx.x * 128 + threadIdx.x;
    if (r >= NROWS) return;

    float S0 = 0.f, S1 = 0.f, S2 = 0.f;
#pragma unroll 8
    for (int ksi = 0; ksi < KSPLIT; ksi++) {
        float4 pp = g_part[(size_t)ksi * NROWS + r];
        S0 += pp.x; S1 += pp.y; S2 += pp.z;
    }

    float s[DQ];
#pragma unroll
    for (int d = 0; d < DQ; d++) {
        float val = W_fc3[d * 2] * S1 + W_fc3[d * 2 + 1] * S2 + b_fc3[d] * S0;
        s[d] = (val > 0.5f) ? val : 0.f;
    }

    int b = r / TN;
    int p = r - b * TN;
    int t = p / V_;
    int v = p - t * V_;

#pragma unroll
    for (int d = 0; d < OUTD; d++) {
        float y = b_out[d];
#pragma unroll
        for (int h = 0; h < DQ; h++) y += W_out[d * DQ + h] * s[h];
        out[((b * OUTD + d) * T_ + t) * V_ + v] = y;
    }
}

// ---------------------------------------------------------------------------
extern "C" void kernel_launch(void* const* d_in, const int* in_sizes, int n_in,
                              void* d_out, int out_size) {
    const float* x       = (const float*)d_in[0];
    const float* coords  = (const float*)d_in[1];
    const float* meta    = (const float*)d_in[2];
    const float* W_ih    = (const float*)d_in[3];
    const float* b_ih    = (const float*)d_in[5];
    const float* b_hh    = (const float*)d_in[6];
    const float* W_comp  = (const float*)d_in[7];
    const float* b_comp  = (const float*)d_in[8];
    const float* W_fuse  = (const float*)d_in[9];
    const float* b_fuse  = (const float*)d_in[10];
    const float* W_fc    = (const float*)d_in[11];
    const float* b_fc    = (const float*)d_in[12];
    const float* W_fc2   = (const float*)d_in[13];
    const float* b_fc2   = (const float*)d_in[14];
    const float* W_fc3   = (const float*)d_in[15];
    const float* b_fc3   = (const float*)d_in[16];
    const float* W_out   = (const float*)d_in[17];
    const float* b_out   = (const float*)d_in[18];
    float* out = (float*)d_out;

    k01<<<CI, 256>>>(W_fuse, W_comp, b_comp, W_fc, W_fc2, b_fc2, meta);
    k1b_reduce<<<8, 32>>>();
    k2_rows<<<80, 128>>>(x, coords, W_ih, b_ih, b_hh, W_fuse, b_fuse,
                         W_fc, b_fc, W_fc2, b_fc2);
    k3_attn<<<dim3(NQB, KSPLIT), K3THR>>>();
    k4_out<<<80, 128>>>(W_fc3, b_fc3, W_out, b_out, out);
}

// round 9
// speedup vs baseline: 1.4199x; 1.4199x over previous
#include <cuda_runtime.h>
#include <cuda_bf16.h>
#include <math.h>

// ---------------------------------------------------------------------------
#define B_     2
#define T_     20
#define V_     256
#define TN     (T_ * V_)          // 5120
#define NROWS  (B_ * TN)         // 10240
#define HID    4
#define DQ     8
#define OUTD   5
#define CMAP   2048
#define HMAP   32
#define WMAP   32
#define NPIX   (HMAP * WMAP)     // 1024
#define CC     256

#define KSPLIT 64
#define KCHUNK (TN / KSPLIT)     // 80
#define QPT    4                 // queries per thread in k3
#define K3THR  128
#define QBLK   (K3THR * QPT)     // 512
#define NQB    (NROWS / QBLK)    // 20

#define W0SPLIT 16
#define C1SPLIT 64

// ---------------------------------------------------------------------------
__device__ float  g_Weffp[W0SPLIT * 4 * CMAP];
__device__ float  g_cb[4];
__device__ float  g_pp[C1SPLIT * 4 * NPIX];
__device__ float4 g_pcomp4[NPIX];
__device__ float4 g_ABG[NROWS];               // (alpha,beta,gamma)*-log2e, pad
__device__ float2 g_UW[NROWS];                // pos-encoded (xr0, xr1)
__device__ float4 g_part[KSPLIT * NROWS];     // (T0,T1,T2,pad) partials

// ---------------------------------------------------------------------------
__device__ __forceinline__ float ex2f(float x) {
    float r; asm("ex2.approx.f32 %0, %1;" : "=f"(r) : "f"(x)); return r;
}
__device__ __forceinline__ float rcpf(float x) {
    float r; asm("rcp.approx.f32 %0, %1;" : "=f"(r) : "f"(x)); return r;
}
__device__ __forceinline__ float fsigm(float x) { return rcpf(1.f + ex2f(-1.44269504f * x)); }
__device__ __forceinline__ float ftanh(float x) { return 1.f - 2.f * rcpf(ex2f(2.88539008f * x) + 1.f); }

// ---------------------------------------------------------------------------
// K0: Weff partials over 16 cc-splits. grid(8, 16) x 256.
// ---------------------------------------------------------------------------
__global__ __launch_bounds__(256) void k0_weff(const float* __restrict__ W_fuse,
                                               const float* __restrict__ W_comp,
                                               const float* __restrict__ b_comp) {
    __shared__ float sw[4 * 16];
    int tid = threadIdx.x, by = blockIdx.y;
    if (tid < 64) {
        int h = tid >> 4, cc = tid & 15;
        sw[tid] = W_fuse[h * 260 + 4 + by * 16 + cc];
    }
    __syncthreads();

    int c = blockIdx.x * 256 + tid;
    float a0 = 0.f, a1 = 0.f, a2 = 0.f, a3 = 0.f;
#pragma unroll
    for (int cc = 0; cc < 16; cc++) {
        float w = W_comp[(by * 16 + cc) * CMAP + c];
        a0 += sw[cc]      * w;
        a1 += sw[16 + cc] * w;
        a2 += sw[32 + cc] * w;
        a3 += sw[48 + cc] * w;
    }
    g_Weffp[(by * 4 + 0) * CMAP + c] = a0;
    g_Weffp[(by * 4 + 1) * CMAP + c] = a1;
    g_Weffp[(by * 4 + 2) * CMAP + c] = a2;
    g_Weffp[(by * 4 + 3) * CMAP + c] = a3;

    if (blockIdx.x == 0 && by == 0 && tid < 32) {
        float p0 = 0.f, p1 = 0.f, p2 = 0.f, p3 = 0.f;
        for (int cc = tid; cc < CC; cc += 32) {
            float bv = b_comp[cc];
            p0 += W_fuse[0 * 260 + 4 + cc] * bv;
            p1 += W_fuse[1 * 260 + 4 + cc] * bv;
            p2 += W_fuse[2 * 260 + 4 + cc] * bv;
            p3 += W_fuse[3 * 260 + 4 + cc] * bv;
        }
#pragma unroll
        for (int o = 16; o > 0; o >>= 1) {
            p0 += __shfl_down_sync(0xffffffffu, p0, o);
            p1 += __shfl_down_sync(0xffffffffu, p1, o);
            p2 += __shfl_down_sync(0xffffffffu, p2, o);
            p3 += __shfl_down_sync(0xffffffffu, p3, o);
        }
        if (tid == 0) { g_cb[0] = p0; g_cb[1] = p1; g_cb[2] = p2; g_cb[3] = p3; }
    }
}

// ---------------------------------------------------------------------------
// K1: pcomp partials over 64 channel chunks of 32. grid(64) x 256.
// ---------------------------------------------------------------------------
__global__ __launch_bounds__(256) void k1_pcomp(const float* __restrict__ metadata) {
    __shared__ float sw[128];
    int tid = threadIdx.x, ci = blockIdx.x;
    if (tid < 128) {
        int h = tid >> 5, cl = tid & 31;
        int c = ci * 32 + cl;
        float s = 0.f;
#pragma unroll
        for (int sp = 0; sp < W0SPLIT; sp++) s += g_Weffp[(sp * 4 + h) * CMAP + c];
        sw[tid] = s;
    }
    __syncthreads();

    const float4* m4 = (const float4*)metadata;
    float4 a0 = make_float4(0, 0, 0, 0), a1 = a0, a2 = a0, a3 = a0;
#pragma unroll 8
    for (int cl = 0; cl < 32; cl++) {
        float4 m = m4[(ci * 32 + cl) * 256 + tid];
        float w0 = sw[cl], w1 = sw[32 + cl], w2 = sw[64 + cl], w3 = sw[96 + cl];
        a0.x += w0 * m.x; a0.y += w0 * m.y; a0.z += w0 * m.z; a0.w += w0 * m.w;
        a1.x += w1 * m.x; a1.y += w1 * m.y; a1.z += w1 * m.z; a1.w += w1 * m.w;
        a2.x += w2 * m.x; a2.y += w2 * m.y; a2.z += w2 * m.z; a2.w += w2 * m.w;
        a3.x += w3 * m.x; a3.y += w3 * m.y; a3.z += w3 * m.z; a3.w += w3 * m.w;
    }
    float4* pp4 = (float4*)g_pp;
    pp4[(ci * 4 + 0) * 256 + tid] = a0;
    pp4[(ci * 4 + 1) * 256 + tid] = a1;
    pp4[(ci * 4 + 2) * 256 + tid] = a2;
    pp4[(ci * 4 + 3) * 256 + tid] = a3;
}

// ---------------------------------------------------------------------------
// K1b: reduce 64 partials + bias. grid(4) x 256.
// ---------------------------------------------------------------------------
__global__ __launch_bounds__(256) void k1b_reduce() {
    int pix = blockIdx.x * 256 + threadIdx.x;
    float s0 = g_cb[0], s1 = g_cb[1], s2 = g_cb[2], s3 = g_cb[3];
#pragma unroll 8
    for (int ci = 0; ci < C1SPLIT; ci++) {
        s0 += g_pp[(ci * 4 + 0) * NPIX + pix];
        s1 += g_pp[(ci * 4 + 1) * NPIX + pix];
        s2 += g_pp[(ci * 4 + 2) * NPIX + pix];
        s3 += g_pp[(ci * 4 + 3) * NPIX + pix];
    }
    g_pcomp4[pix] = make_float4(s0, s1, s2, s3);
}

// ---------------------------------------------------------------------------
// K2: per-row pos-encode, LSTM, bilinear sample, fuse, Q -> (alpha,beta,gamma)
// plus (u,w). grid(80) x 128.
// ---------------------------------------------------------------------------
__global__ __launch_bounds__(128) void k2_rows(
        const float* __restrict__ x,
        const float* __restrict__ coords,
        const float* __restrict__ W_ih,
        const float* __restrict__ b_ih,
        const float* __restrict__ b_hh,
        const float* __restrict__ W_fuse,
        const float* __restrict__ b_fuse,
        const float* __restrict__ W_fc,
        const float* __restrict__ b_fc,
        const float* __restrict__ W_fc2,
        const float* __restrict__ b_fc2) {
    __shared__ float sW_ih[32], sb[16], sWf4[16], sbf[4];
    __shared__ float sW_fc[32], sb_fc[8], sW2a[8], sW2b[8], sb2[8];
    int tid = threadIdx.x;
    if (tid < 32) sW_ih[tid] = W_ih[tid];
    if (tid < 16) sb[tid] = b_ih[tid] + b_hh[tid];
    if (tid < 16) sWf4[tid] = W_fuse[(tid >> 2) * 260 + (tid & 3)];
    if (tid < 4)  sbf[tid] = b_fuse[tid];
    if (tid < 32) sW_fc[tid] = W_fc[tid];
    if (tid < 8)  sb_fc[tid] = b_fc[tid];
    if (tid < 8)  sW2a[tid] = W_fc2[tid * 2];
    if (tid < 8)  sW2b[tid] = W_fc2[tid * 2 + 1];
    if (tid < 8)  sb2[tid] = b_fc2[tid];
    __syncthreads();

    int r = blockIdx.x * 128 + tid;
    if (r >= NROWS) return;
    int b = r / TN;
    int p = r - b * TN;
    int t = p / V_;
    int v = p - t * V_;

    float tf  = (float)t;
    float xr0 = x[r * 2 + 0] + __sinf(tf);
    float xr1 = x[r * 2 + 1] + __cosf(tf);
    g_UW[r] = make_float2(xr0, xr1);

    float X[HID];
#pragma unroll
    for (int h = 0; h < HID; h++) {
        int ji = h, jg = 8 + h, jo = 12 + h;
        float gi = sW_ih[ji * 2] * xr0 + sW_ih[ji * 2 + 1] * xr1 + sb[ji];
        float gg = sW_ih[jg * 2] * xr0 + sW_ih[jg * 2 + 1] * xr1 + sb[jg];
        float go = sW_ih[jo * 2] * xr0 + sW_ih[jo * 2 + 1] * xr1 + sb[jo];
        float cst = fsigm(gi) * ftanh(gg);
        X[h] = fsigm(go) * ftanh(cst);
    }

    float cx = coords[((b * 2 + 0) * T_ + t) * V_ + v];
    float cy = coords[((b * 2 + 1) * T_ + t) * V_ + v];
    float fx = cx * (1.f / 16.f) - 0.5f;
    float fy = cy * (1.f / 16.f) - 0.5f;
    float x0f = floorf(fx), y0f = floorf(fy);
    int ix0 = (int)x0f, iy0 = (int)y0f;
    float wx1 = fx - x0f, wx0 = 1.f - wx1;
    float wy1 = fy - y0f, wy0 = 1.f - wy1;

    float l0 = 0.f, l1 = 0.f, l2 = 0.f, l3 = 0.f;
#pragma unroll
    for (int cyi = 0; cyi < 2; cyi++) {
#pragma unroll
        for (int cxi = 0; cxi < 2; cxi++) {
            int iy = iy0 + cyi, ix = ix0 + cxi;
            if (iy >= 0 && iy < HMAP && ix >= 0 && ix < WMAP) {
                float w = (cyi ? wy1 : wy0) * (cxi ? wx1 : wx0);
                float4 pv = g_pcomp4[iy * WMAP + ix];
                l0 += w * pv.x; l1 += w * pv.y; l2 += w * pv.z; l3 += w * pv.w;
            }
        }
    }

    float fsd[HID];
#pragma unroll
    for (int h = 0; h < HID; h++) {
        float s = sbf[h];
#pragma unroll
        for (int j = 0; j < HID; j++) s += sWf4[h * 4 + j] * X[j];
        fsd[h] = s + (h == 0 ? l0 : (h == 1 ? l1 : (h == 2 ? l2 : l3)));
    }

    float al = 0.f, be = 0.f, ga = 0.f;
#pragma unroll
    for (int d = 0; d < DQ; d++) {
        float q = sb_fc[d];
#pragma unroll
        for (int h = 0; h < HID; h++) q += sW_fc[d * HID + h] * fsd[h];
        al += q * sW2a[d];
        be += q * sW2b[d];
        ga += q * sb2[d];
    }
    const float NL2E = -1.44269504f;
    g_ABG[r] = make_float4(al * NL2E, be * NL2E, ga * NL2E, 0.f);
}

// ---------------------------------------------------------------------------
// K3: rank-2 sigmoid attention. grid(NQB=20, KSPLIT=64) x 128, 4 q/thread.
// Per pair: d = a*u + b*w + g (2 FMA); pr = rcp(1+ex2(d)) (FADD+2 MUFU);
// T0+=pr, T1+=pr*u, T2+=pr*w (FADD+2 FMA). MUFU-throughput-bound.
// ---------------------------------------------------------------------------
__global__ __launch_bounds__(K3THR) void k3_attn() {
    __shared__ float2 suw[KCHUNK];
    int bq  = blockIdx.x;
    int ks  = blockIdx.y;
    int tid = threadIdx.x;
    int b   = bq / (NQB / B_);
    int kbase = b * TN + ks * KCHUNK;

    if (tid < KCHUNK) suw[tid] = g_UW[kbase + tid];
    __syncthreads();

    int r = bq * QBLK + tid * QPT;

    float qa[QPT], qb[QPT], qg[QPT];
#pragma unroll
    for (int i = 0; i < QPT; i++) {
        float4 abg = g_ABG[r + i];
        qa[i] = abg.x; qb[i] = abg.y; qg[i] = abg.z;
    }

    float T0[QPT], T1[QPT], T2[QPT];
#pragma unroll
    for (int i = 0; i < QPT; i++) { T0[i] = 0.f; T1[i] = 0.f; T2[i] = 0.f; }

#pragma unroll 8
    for (int j = 0; j < KCHUNK; j++) {
        float2 uw = suw[j];
        float u = uw.x, w = uw.y;
        float e[QPT], pr[QPT];
#pragma unroll
        for (int i = 0; i < QPT; i++) {
            float d = fmaf(qa[i], u, qg[i]);
            d = fmaf(qb[i], w, d);
            e[i] = ex2f(d);
        }
#pragma unroll
        for (int i = 0; i < QPT; i++) pr[i] = rcpf(1.f + e[i]);
#pragma unroll
        for (int i = 0; i < QPT; i++) {
            T0[i] += pr[i];
            T1[i] = fmaf(pr[i], u, T1[i]);
            T2[i] = fmaf(pr[i], w, T2[i]);
        }
    }

    float4* dst = g_part + (size_t)ks * NROWS + r;
#pragma unroll
    for (int i = 0; i < QPT; i++)
        dst[i] = make_float4(T0[i], T1[i], T2[i], 0.f);
}

// ---------------------------------------------------------------------------
// K4: reduce 64 T partials, reconstruct 8-dim, threshold, project. grid(80)x128
// ---------------------------------------------------------------------------
__global__ __launch_bounds__(128) void k4_out(const float* __restrict__ W_fc3,
                                              const float* __restrict__ b_fc3,
                                              const float* __restrict__ W_out,
                                              const float* __restrict__ b_out,
                                              float* __restrict__ out) {
    int r = blockIdx.x * 128 + threadIdx.x;
    if (r >= NROWS) return;

    float S0 = 0.f, S1 = 0.f, S2 = 0.f;
#pragma unroll 8
    for (int ksi = 0; ksi < KSPLIT; ksi++) {
        float4 pp = g_part[(size_t)ksi * NROWS + r];
        S0 += pp.x; S1 += pp.y; S2 += pp.z;
    }

    float s[DQ];
#pragma unroll
    for (int d = 0; d < DQ; d++) {
        float val = W_fc3[d * 2] * S1 + W_fc3[d * 2 + 1] * S2 + b_fc3[d] * S0;
        s[d] = (val > 0.5f) ? val : 0.f;
    }

    int b = r / TN;
    int p = r - b * TN;
    int t = p / V_;
    int v = p - t * V_;

#pragma unroll
    for (int d = 0; d < OUTD; d++) {
        float y = b_out[d];
#pragma unroll
        for (int h = 0; h < DQ; h++) y += W_out[d * DQ + h] * s[h];
        out[((b * OUTD + d) * T_ + t) * V_ + v] = y;
    }
}

// ---------------------------------------------------------------------------
extern "C" void kernel_launch(void* const* d_in, const int* in_sizes, int n_in,
                              void* d_out, int out_size) {
    const float* x       = (const float*)d_in[0];
    const float* coords  = (const float*)d_in[1];
    const float* meta    = (const float*)d_in[2];
    const float* W_ih    = (const float*)d_in[3];
    const float* b_ih    = (const float*)d_in[5];
    const float* b_hh    = (const float*)d_in[6];
    const float* W_comp  = (const float*)d_in[7];
    const float* b_comp  = (const float*)d_in[8];
    const float* W_fuse  = (const float*)d_in[9];
    const float* b_fuse  = (const float*)d_in[10];
    const float* W_fc    = (const float*)d_in[11];
    const float* b_fc    = (const float*)d_in[12];
    const float* W_fc2   = (const float*)d_in[13];
    const float* b_fc2   = (const float*)d_in[14];
    const float* W_fc3   = (const float*)d_in[15];
    const float* b_fc3   = (const float*)d_in[16];
    const float* W_out   = (const float*)d_in[17];
    const float* b_out   = (const float*)d_in[18];
    float* out = (float*)d_out;

    k0_weff<<<dim3(8, W0SPLIT), 256>>>(W_fuse, W_comp, b_comp);
    k1_pcomp<<<C1SPLIT, 256>>>(meta);
    k1b_reduce<<<4, 256>>>();
    k2_rows<<<80, 128>>>(x, coords, W_ih, b_ih, b_hh, W_fuse, b_fuse,
                         W_fc, b_fc, W_fc2, b_fc2);
    k3_attn<<<dim3(NQB, KSPLIT), K3THR>>>();
    k4_out<<<80, 128>>>(W_fc3, b_fc3, W_out, b_out, out);
}

// round 10
// speedup vs baseline: 1.4952x; 1.0531x over previous
#include <cuda_runtime.h>
#include <cuda_bf16.h>
#include <math.h>

// ---------------------------------------------------------------------------
#define B_     2
#define T_     20
#define V_     256
#define TN     (T_ * V_)          // 5120
#define NROWS  (B_ * TN)         // 10240
#define HID    4
#define DQ     8
#define OUTD   5
#define CMAP   2048
#define HMAP   32
#define WMAP   32
#define NPIX   (HMAP * WMAP)     // 1024
#define CC     256

#define KSPLIT 64
#define KCHUNK (TN / KSPLIT)     // 80
#define QPT    4                 // queries per thread in k3
#define K3THR  128
#define QBLK   (K3THR * QPT)     // 512
#define NQB    (NROWS / QBLK)    // 20

#define C1SPLIT 64               // channel chunks (32 ch each) in k1f

// ---------------------------------------------------------------------------
__device__ float  g_cb[4];
__device__ float  g_pp[C1SPLIT * 4 * NPIX];
__device__ float4 g_pcomp4[NPIX];
__device__ float4 g_ABG[NROWS];               // (alpha,beta,gamma)*-log2e, pad
__device__ float2 g_UW[NROWS];                // pos-encoded (xr0, xr1)
__device__ float4 g_part[KSPLIT * NROWS];     // (T0,T1,T2,pad) partials

// ---------------------------------------------------------------------------
__device__ __forceinline__ float ex2f(float x) {
    float r; asm("ex2.approx.f32 %0, %1;" : "=f"(r) : "f"(x)); return r;
}
__device__ __forceinline__ float rcpf(float x) {
    float r; asm("rcp.approx.f32 %0, %1;" : "=f"(r) : "f"(x)); return r;
}
__device__ __forceinline__ float fsigm(float x) { return rcpf(1.f + ex2f(-1.44269504f * x)); }
__device__ __forceinline__ float ftanh(float x) { return 1.f - 2.f * rcpf(ex2f(2.88539008f * x) + 1.f); }

// ---------------------------------------------------------------------------
// K1f: fused Weff + pcomp partial. grid(64) x 256.
// Block ci owns channels [ci*32, ci*32+32). Phase 1 computes Weff[4][32] for
// its slice directly (warp w covers cc in [w*32,w*32+32)), phase 2 does the
// metadata contraction for those channels.
// ---------------------------------------------------------------------------
__global__ __launch_bounds__(256) void k1f(const float* __restrict__ W_fuse,
                                           const float* __restrict__ W_comp,
                                           const float* __restrict__ b_comp,
                                           const float* __restrict__ metadata) {
    __shared__ float sWfl[4 * 256];   // W_fuse[:, 4:260]
    __shared__ float sW8[8][128];     // per-warp Weff partials
    __shared__ float sw[128];         // Weff[h][cl] for this slice
    int tid = threadIdx.x, ci = blockIdx.x;
    int warp = tid >> 5, lane = tid & 31;

    for (int i = tid; i < 4 * 256; i += 256) {
        int h = i >> 8, cc = i & 255;
        sWfl[i] = W_fuse[h * 260 + 4 + cc];
    }
    __syncthreads();

    // phase 1: warp w sums cc in [w*32, w*32+32) for all 4 h, column = lane
    {
        float a0 = 0.f, a1 = 0.f, a2 = 0.f, a3 = 0.f;
        const float* base = W_comp + ci * 32 + lane;
#pragma unroll
        for (int k = 0; k < 32; k++) {
            int cc = warp * 32 + k;
            float wv = base[cc * CMAP];
            a0 += sWfl[cc]       * wv;
            a1 += sWfl[256 + cc] * wv;
            a2 += sWfl[512 + cc] * wv;
            a3 += sWfl[768 + cc] * wv;
        }
        sW8[warp][0 * 32 + lane] = a0;
        sW8[warp][1 * 32 + lane] = a1;
        sW8[warp][2 * 32 + lane] = a2;
        sW8[warp][3 * 32 + lane] = a3;
    }
    __syncthreads();

    if (tid < 128) {
        float s = 0.f;
#pragma unroll
        for (int wp = 0; wp < 8; wp++) s += sW8[wp][tid];
        sw[tid] = s;
    }

    // bias path: block 0, warp 4 (concurrent with the reduce above)
    if (ci == 0 && warp == 4) {
        float p0 = 0.f, p1 = 0.f, p2 = 0.f, p3 = 0.f;
        for (int cc = lane; cc < CC; cc += 32) {
            float bv = b_comp[cc];
            p0 += sWfl[cc]       * bv;
            p1 += sWfl[256 + cc] * bv;
            p2 += sWfl[512 + cc] * bv;
            p3 += sWfl[768 + cc] * bv;
        }
#pragma unroll
        for (int o = 16; o > 0; o >>= 1) {
            p0 += __shfl_down_sync(0xffffffffu, p0, o);
            p1 += __shfl_down_sync(0xffffffffu, p1, o);
            p2 += __shfl_down_sync(0xffffffffu, p2, o);
            p3 += __shfl_down_sync(0xffffffffu, p3, o);
        }
        if (lane == 0) { g_cb[0] = p0; g_cb[1] = p1; g_cb[2] = p2; g_cb[3] = p3; }
    }
    __syncthreads();

    // phase 2: pcomp partial for this 32-channel slice; thread = 4-pixel group
    const float4* m4 = (const float4*)metadata;
    float4 a0 = make_float4(0, 0, 0, 0), a1 = a0, a2 = a0, a3 = a0;
#pragma unroll 8
    for (int cl = 0; cl < 32; cl++) {
        float4 m = m4[(ci * 32 + cl) * 256 + tid];
        float w0 = sw[cl], w1 = sw[32 + cl], w2 = sw[64 + cl], w3 = sw[96 + cl];
        a0.x += w0 * m.x; a0.y += w0 * m.y; a0.z += w0 * m.z; a0.w += w0 * m.w;
        a1.x += w1 * m.x; a1.y += w1 * m.y; a1.z += w1 * m.z; a1.w += w1 * m.w;
        a2.x += w2 * m.x; a2.y += w2 * m.y; a2.z += w2 * m.z; a2.w += w2 * m.w;
        a3.x += w3 * m.x; a3.y += w3 * m.y; a3.z += w3 * m.z; a3.w += w3 * m.w;
    }
    float4* pp4 = (float4*)g_pp;
    pp4[(ci * 4 + 0) * 256 + tid] = a0;
    pp4[(ci * 4 + 1) * 256 + tid] = a1;
    pp4[(ci * 4 + 2) * 256 + tid] = a2;
    pp4[(ci * 4 + 3) * 256 + tid] = a3;
}

// ---------------------------------------------------------------------------
// K1b: reduce 64 partials + bias. grid(4) x 256.
// ---------------------------------------------------------------------------
__global__ __launch_bounds__(256) void k1b_reduce() {
    int pix = blockIdx.x * 256 + threadIdx.x;
    float s0 = g_cb[0], s1 = g_cb[1], s2 = g_cb[2], s3 = g_cb[3];
#pragma unroll 8
    for (int ci = 0; ci < C1SPLIT; ci++) {
        s0 += g_pp[(ci * 4 + 0) * NPIX + pix];
        s1 += g_pp[(ci * 4 + 1) * NPIX + pix];
        s2 += g_pp[(ci * 4 + 2) * NPIX + pix];
        s3 += g_pp[(ci * 4 + 3) * NPIX + pix];
    }
    g_pcomp4[pix] = make_float4(s0, s1, s2, s3);
}

// ---------------------------------------------------------------------------
// K2: per-row pos-encode, LSTM, bilinear sample, fuse -> (alpha,beta,gamma),
// (u,w). grid(80) x 128. Input LDGs issued BEFORE the smem staging barrier.
// ---------------------------------------------------------------------------
__global__ __launch_bounds__(128) void k2_rows(
        const float* __restrict__ x,
        const float* __restrict__ coords,
        const float* __restrict__ W_ih,
        const float* __restrict__ b_ih,
        const float* __restrict__ b_hh,
        const float* __restrict__ W_fuse,
        const float* __restrict__ b_fuse,
        const float* __restrict__ W_fc,
        const float* __restrict__ b_fc,
        const float* __restrict__ W_fc2,
        const float* __restrict__ b_fc2) {
    __shared__ float sW_ih[32], sb[16], sWf4[16], sbf[4];
    __shared__ float sW_fc[32], sb_fc[8], sW2a[8], sW2b[8], sb2[8];
    int tid = threadIdx.x;
    int r = blockIdx.x * 128 + tid;
    int b = r / TN;
    int p = r - b * TN;
    int t = p / V_;
    int v = p - t * V_;

    // hoisted input loads (DRAM latency overlaps staging below)
    float2 xin = ((const float2*)x)[r];
    float cx = coords[((b * 2 + 0) * T_ + t) * V_ + v];
    float cy = coords[((b * 2 + 1) * T_ + t) * V_ + v];

    if (tid < 32) sW_ih[tid] = W_ih[tid];
    if (tid < 16) sb[tid] = b_ih[tid] + b_hh[tid];
    if (tid < 16) sWf4[tid] = W_fuse[(tid >> 2) * 260 + (tid & 3)];
    if (tid < 4)  sbf[tid] = b_fuse[tid];
    if (tid < 32) sW_fc[tid] = W_fc[tid];
    if (tid < 8)  sb_fc[tid] = b_fc[tid];
    if (tid < 8)  sW2a[tid] = W_fc2[tid * 2];
    if (tid < 8)  sW2b[tid] = W_fc2[tid * 2 + 1];
    if (tid < 8)  sb2[tid] = b_fc2[tid];
    __syncthreads();

    float tf  = (float)t;
    float xr0 = xin.x + __sinf(tf);
    float xr1 = xin.y + __cosf(tf);
    g_UW[r] = make_float2(xr0, xr1);

    float X[HID];
#pragma unroll
    for (int h = 0; h < HID; h++) {
        int ji = h, jg = 8 + h, jo = 12 + h;
        float gi = sW_ih[ji * 2] * xr0 + sW_ih[ji * 2 + 1] * xr1 + sb[ji];
        float gg = sW_ih[jg * 2] * xr0 + sW_ih[jg * 2 + 1] * xr1 + sb[jg];
        float go = sW_ih[jo * 2] * xr0 + sW_ih[jo * 2 + 1] * xr1 + sb[jo];
        float cst = fsigm(gi) * ftanh(gg);
        X[h] = fsigm(go) * ftanh(cst);
    }

    float fx = cx * (1.f / 16.f) - 0.5f;
    float fy = cy * (1.f / 16.f) - 0.5f;
    float x0f = floorf(fx), y0f = floorf(fy);
    int ix0 = (int)x0f, iy0 = (int)y0f;
    float wx1 = fx - x0f, wx0 = 1.f - wx1;
    float wy1 = fy - y0f, wy0 = 1.f - wy1;

    float l0 = 0.f, l1 = 0.f, l2 = 0.f, l3 = 0.f;
#pragma unroll
    for (int cyi = 0; cyi < 2; cyi++) {
#pragma unroll
        for (int cxi = 0; cxi < 2; cxi++) {
            int iy = iy0 + cyi, ix = ix0 + cxi;
            if (iy >= 0 && iy < HMAP && ix >= 0 && ix < WMAP) {
                float w = (cyi ? wy1 : wy0) * (cxi ? wx1 : wx0);
                float4 pv = g_pcomp4[iy * WMAP + ix];
                l0 += w * pv.x; l1 += w * pv.y; l2 += w * pv.z; l3 += w * pv.w;
            }
        }
    }

    float fsd[HID];
#pragma unroll
    for (int h = 0; h < HID; h++) {
        float s = sbf[h];
#pragma unroll
        for (int j = 0; j < HID; j++) s += sWf4[h * 4 + j] * X[j];
        fsd[h] = s + (h == 0 ? l0 : (h == 1 ? l1 : (h == 2 ? l2 : l3)));
    }

    float al = 0.f, be = 0.f, ga = 0.f;
#pragma unroll
    for (int d = 0; d < DQ; d++) {
        float q = sb_fc[d];
#pragma unroll
        for (int h = 0; h < HID; h++) q += sW_fc[d * HID + h] * fsd[h];
        al += q * sW2a[d];
        be += q * sW2b[d];
        ga += q * sb2[d];
    }
    const float NL2E = -1.44269504f;
    g_ABG[r] = make_float4(al * NL2E, be * NL2E, ga * NL2E, 0.f);
}

// ---------------------------------------------------------------------------
// K3: rank-2 sigmoid attention. grid(20, 64) x 128, 4 q/thread.
// Pair-rcp: queries (0,1) and (2,3) share one rcp each:
//   pr0 = den1 * rcp(den0*den1), pr1 = den0 * rcp(den0*den1).
// Per iter: MUFU 6 (was 8), FMA-pipe 30 (was 24).
// ---------------------------------------------------------------------------
__global__ __launch_bounds__(K3THR) void k3_attn() {
    __shared__ float2 suw[KCHUNK];
    int bq  = blockIdx.x;
    int ks  = blockIdx.y;
    int tid = threadIdx.x;
    int b   = bq / (NQB / B_);
    int kbase = b * TN + ks * KCHUNK;

    if (tid < KCHUNK) suw[tid] = g_UW[kbase + tid];
    __syncthreads();

    int r = bq * QBLK + tid * QPT;

    float qa[QPT], qb[QPT], qg[QPT];
#pragma unroll
    for (int i = 0; i < QPT; i++) {
        float4 abg = g_ABG[r + i];
        qa[i] = abg.x; qb[i] = abg.y; qg[i] = abg.z;
    }

    float T0[QPT], T1[QPT], T2[QPT];
#pragma unroll
    for (int i = 0; i < QPT; i++) { T0[i] = 0.f; T1[i] = 0.f; T2[i] = 0.f; }

#pragma unroll 8
    for (int j = 0; j < KCHUNK; j++) {
        float2 uw = suw[j];
        float u = uw.x, w = uw.y;
        float den[QPT];
#pragma unroll
        for (int i = 0; i < QPT; i++) {
            float d = fmaf(qa[i], u, qg[i]);
            d = fmaf(qb[i], w, d);
            den[i] = 1.f + ex2f(d);
        }
        float r01 = rcpf(den[0] * den[1]);
        float r23 = rcpf(den[2] * den[3]);
        float pr[QPT];
        pr[0] = den[1] * r01;
        pr[1] = den[0] * r01;
        pr[2] = den[3] * r23;
        pr[3] = den[2] * r23;
#pragma unroll
        for (int i = 0; i < QPT; i++) {
            T0[i] += pr[i];
            T1[i] = fmaf(pr[i], u, T1[i]);
            T2[i] = fmaf(pr[i], w, T2[i]);
        }
    }

    float4* dst = g_part + (size_t)ks * NROWS + r;
#pragma unroll
    for (int i = 0; i < QPT; i++)
        dst[i] = make_float4(T0[i], T1[i], T2[i], 0.f);
}

// ---------------------------------------------------------------------------
// K4: reduce 64 T partials, reconstruct 8-dim, threshold, project. grid(80)x128
// ---------------------------------------------------------------------------
__global__ __launch_bounds__(128) void k4_out(const float* __restrict__ W_fc3,
                                              const float* __restrict__ b_fc3,
                                              const float* __restrict__ W_out,
                                              const float* __restrict__ b_out,
                                              float* __restrict__ out) {
    int r = blockIdx.x * 128 + threadIdx.x;
    if (r >= NROWS) return;

    float S0 = 0.f, S1 = 0.f, S2 = 0.f;
#pragma unroll 8
    for (int ksi = 0; ksi < KSPLIT; ksi++) {
        float4 pp = g_part[(size_t)ksi * NROWS + r];
        S0 += pp.x; S1 += pp.y; S2 += pp.z;
    }

    float s[DQ];
#pragma unroll
    for (int d = 0; d < DQ; d++) {
        float val = W_fc3[d * 2] * S1 + W_fc3[d * 2 + 1] * S2 + b_fc3[d] * S0;
        s[d] = (val > 0.5f) ? val : 0.f;
    }

    int b = r / TN;
    int p = r - b * TN;
    int t = p / V_;
    int v = p - t * V_;

#pragma unroll
    for (int d = 0; d < OUTD; d++) {
        float y = b_out[d];
#pragma unroll
        for (int h = 0; h < DQ; h++) y += W_out[d * DQ + h] * s[h];
        out[((b * OUTD + d) * T_ + t) * V_ + v] = y;
    }
}

// ---------------------------------------------------------------------------
extern "C" void kernel_launch(void* const* d_in, const int* in_sizes, int n_in,
                              void* d_out, int out_size) {
    const float* x       = (const float*)d_in[0];
    const float* coords  = (const float*)d_in[1];
    const float* meta    = (const float*)d_in[2];
    const float* W_ih    = (const float*)d_in[3];
    const float* b_ih    = (const float*)d_in[5];
    const float* b_hh    = (const float*)d_in[6];
    const float* W_comp  = (const float*)d_in[7];
    const float* b_comp  = (const float*)d_in[8];
    const float* W_fuse  = (const float*)d_in[9];
    const float* b_fuse  = (const float*)d_in[10];
    const float* W_fc    = (const float*)d_in[11];
    const float* b_fc    = (const float*)d_in[12];
    const float* W_fc2   = (const float*)d_in[13];
    const float* b_fc2   = (const float*)d_in[14];
    const float* W_fc3   = (const float*)d_in[15];
    const float* b_fc3   = (const float*)d_in[16];
    const float* W_out   = (const float*)d_in[17];
    const float* b_out   = (const float*)d_in[18];
    float* out = (float*)d_out;

    k1f<<<C1SPLIT, 256>>>(W_fuse, W_comp, b_comp, meta);
    k1b_reduce<<<4, 256>>>();
    k2_rows<<<80, 128>>>(x, coords, W_ih, b_ih, b_hh, W_fuse, b_fuse,
                         W_fc, b_fc, W_fc2, b_fc2);
    k3_attn<<<dim3(NQB, KSPLIT), K3THR>>>();
    k4_out<<<80, 128>>>(W_fc3, b_fc3, W_out, b_out, out);
}